// round 14
// baseline (speedup 1.0000x reference)
#include <cuda_runtime.h>
#include <cuda_bf16.h>
#include <math.h>
#include <stdint.h>

// ---------------- problem constants ----------------
#define BATCH   2
#define LSEQ    1024
#define DMODEL  1024
#define DINNER  2048
#define DSTATE  16
#define DTRANK  64
#define NXZ     (2*DINNER)           // 4096
#define NDBL    (DTRANK + 2*DSTATE)  // 96
#define MROWS   (BATCH*LSEQ)         // 2048
#define NCHUNK  16
#define CLEN    64                   // LSEQ / NCHUNK

// ---------------- scratch (static device memory; no allocation) ----------------
__device__ float g_xn  [MROWS * DMODEL];
__device__ float g_xz  [MROWS * NXZ];
__device__ float g_xc  [MROWS * DINNER];
__device__ float g_xdbl[MROWS * NDBL];
__device__ float g_dt  [MROWS * DINNER];
__device__ float g_yout[MROWS * DINNER];
__device__ float g_Ap  [BATCH * NCHUNK * DSTATE * DINNER];
__device__ float g_Hp  [BATCH * NCHUNK * DSTATE * DINNER];
__device__ float g_hin [BATCH * NCHUNK * DSTATE * DINNER];

// ---------------- transpose (B,C,L) -> (B,L,C) ----------------
__global__ void transpose_k(const float* __restrict__ x, float* __restrict__ xt)
{
    __shared__ float t[32][33];
    const int b  = blockIdx.z;
    const int c0 = blockIdx.y * 32;
    const int l0 = blockIdx.x * 32;
    #pragma unroll
    for (int i = threadIdx.y; i < 32; i += 8)
        t[i][threadIdx.x] = x[(size_t)b*DMODEL*LSEQ + (size_t)(c0+i)*LSEQ + l0 + threadIdx.x];
    __syncthreads();
    #pragma unroll
    for (int i = threadIdx.y; i < 32; i += 8)
        xt[(size_t)b*LSEQ*DMODEL + (size_t)(l0+i)*DMODEL + c0 + threadIdx.x] = t[threadIdx.x][i];
}

// ---------------- layernorm over channel dim, in place ----------------
__global__ void ln_k(float* __restrict__ xn, const float* __restrict__ w,
                     const float* __restrict__ bsh)
{
    const int m = blockIdx.x;
    float* row = xn + (size_t)m * DMODEL;
    __shared__ float sm[DMODEL];
    __shared__ float rs[8], rs2[8];
    __shared__ float s_mu, s_rstd;
    const int tid = threadIdx.x;   // 256

    float s = 0.f, s2 = 0.f;
    #pragma unroll
    for (int i = tid; i < DMODEL; i += 256) {
        float v = row[i];
        sm[i] = v;
        s += v;
        s2 = fmaf(v, v, s2);
    }
    #pragma unroll
    for (int o = 16; o > 0; o >>= 1) {
        s  += __shfl_xor_sync(0xffffffffu, s,  o);
        s2 += __shfl_xor_sync(0xffffffffu, s2, o);
    }
    if ((tid & 31) == 0) { rs[tid >> 5] = s; rs2[tid >> 5] = s2; }
    __syncthreads();
    if (tid == 0) {
        float S = 0.f, S2 = 0.f;
        #pragma unroll
        for (int i = 0; i < 8; i++) { S += rs[i]; S2 += rs2[i]; }
        float mu  = S * (1.0f / DMODEL);
        float var = S2 * (1.0f / DMODEL) - mu * mu;
        s_mu = mu;
        s_rstd = rsqrtf(var + 1e-5f);
    }
    __syncthreads();
    const float mu = s_mu, r = s_rstd;
    #pragma unroll
    for (int i = tid; i < DMODEL; i += 256)
        row[i] = (sm[i] - mu) * r * w[i] + bsh[i];
}

// ---------------- bf16x2-split helpers ----------------
// (hi, lo) bf16 decomposition packed as bf16x2 pairs over adjacent k.
__device__ __forceinline__ uint2 splitbf2(float x, float y)
{
    __nv_bfloat162 h = __floats2bfloat162_rn(x, y);
    float rx = x - __bfloat162float(h.x);
    float ry = y - __bfloat162float(h.y);
    __nv_bfloat162 l = __floats2bfloat162_rn(rx, ry);
    uint2 r;
    r.x = *reinterpret_cast<uint32_t*>(&h);
    r.y = *reinterpret_cast<uint32_t*>(&l);
    return r;
}
__device__ __forceinline__ void mma_bf16(float* c,
    uint32_t a0, uint32_t a1, uint32_t a2, uint32_t a3,
    uint32_t b0, uint32_t b1)
{
    asm volatile(
        "mma.sync.aligned.m16n8k16.row.col.f32.bf16.bf16.f32 "
        "{%0,%1,%2,%3}, {%4,%5,%6,%7}, {%8,%9}, {%0,%1,%2,%3};"
        : "+f"(c[0]), "+f"(c[1]), "+f"(c[2]), "+f"(c[3])
        : "r"(a0), "r"(a1), "r"(a2), "r"(a3), "r"(b0), "r"(b1));
}

// ---------------- tensor-core GEMM (bf16x3, double-buffered) ----------------
// C[m][n] = sum_k A[m][k] * W[n][k]
// EPI: 0 plain, 1 softplus(acc+bias[n]), 2 transpose-store + residual into d_out
template<int BM, int BN, int WM, int WN, int EPI>
__global__ void __launch_bounds__(256)
tgemm_k(const float* __restrict__ A, int lda,
        const float* __restrict__ W,
        float* __restrict__ C,
        int M, int N, int K,
        const float* __restrict__ ep_bias,
        const float* __restrict__ ep_res)
{
    constexpr int BK   = 32;         // k per tile (2 mma k-steps of 16)
    constexpr int ROWW = 20;         // uint2 per row (16 data + 4 pad) -> 40 words == 8 mod 32
    constexpr int ASZ  = BM * ROWW;
    constexpr int BSZ  = BN * ROWW;
    constexpr int WTM  = BM / WM;
    constexpr int WTN  = BN / WN;
    constexpr int MF   = WTM / 16;
    constexpr int NF   = WTN / 8;
    constexpr int AL   = (BM * 8 + 255) / 256;   // float4 loads per thread (A, 8 per row)
    constexpr int BL   = (BN * 8 + 255) / 256;

    extern __shared__ uint2 smbuf[];
    uint2* As = smbuf;               // [2][ASZ]
    uint2* Bs = smbuf + 2 * ASZ;     // [2][BSZ]

    const int tid  = threadIdx.x;
    const int warp = tid >> 5;
    const int lane = tid & 31;
    const int grp  = lane >> 2;
    const int tid4 = lane & 3;
    const int warpM = warp % WM;
    const int warpN = warp / WM;
    const int mBase = warpM * WTM;
    const int nBase = warpN * WTN;
    const int m0 = blockIdx.y * BM;
    const int n0 = blockIdx.x * BN;

    float acc[MF][NF][4];
    #pragma unroll
    for (int i = 0; i < MF; i++)
        #pragma unroll
        for (int j = 0; j < NF; j++)
            #pragma unroll
            for (int r = 0; r < 4; r++) acc[i][j][r] = 0.f;

    float4 pa[AL], pb[BL];

    auto ldg_tile = [&](int k0) {
        #pragma unroll
        for (int i = 0; i < AL; i++) {
            const int t = tid + i * 256;
            if (t < BM * 8) {
                const int row = t >> 3, cv = t & 7;
                pa[i] = *reinterpret_cast<const float4*>(
                    A + (size_t)(m0 + row) * lda + k0 + cv * 4);
            }
        }
        #pragma unroll
        for (int i = 0; i < BL; i++) {
            const int t = tid + i * 256;
            if (t < BN * 8) {
                const int row = t >> 3, cv = t & 7;
                float4 v = make_float4(0.f, 0.f, 0.f, 0.f);
                if (n0 + row < N)
                    v = *reinterpret_cast<const float4*>(
                        W + (size_t)(n0 + row) * K + k0 + cv * 4);
                pb[i] = v;
            }
        }
    };
    auto sts_tile = [&](int buf) {
        #pragma unroll
        for (int i = 0; i < AL; i++) {
            const int t = tid + i * 256;
            if (t < BM * 8) {
                const int row = t >> 3, cv = t & 7;
                uint2 u0 = splitbf2(pa[i].x, pa[i].y);
                uint2 u1 = splitbf2(pa[i].z, pa[i].w);
                *reinterpret_cast<uint4*>(&As[buf * ASZ + row * ROWW + cv * 2]) =
                    make_uint4(u0.x, u0.y, u1.x, u1.y);
            }
        }
        #pragma unroll
        for (int i = 0; i < BL; i++) {
            const int t = tid + i * 256;
            if (t < BN * 8) {
                const int row = t >> 3, cv = t & 7;
                uint2 u0 = splitbf2(pb[i].x, pb[i].y);
                uint2 u1 = splitbf2(pb[i].z, pb[i].w);
                *reinterpret_cast<uint4*>(&Bs[buf * BSZ + row * ROWW + cv * 2]) =
                    make_uint4(u0.x, u0.y, u1.x, u1.y);
            }
        }
    };

    const int KT = K / BK;

    ldg_tile(0);
    sts_tile(0);
    __syncthreads();

    for (int it = 0; it < KT; it++) {
        if (it + 1 < KT) ldg_tile((it + 1) * BK);

        const uint2* Ab = &As[(it & 1) * ASZ];
        const uint2* Bb = &Bs[(it & 1) * BSZ];

        #pragma unroll
        for (int ks = 0; ks < 2; ks++) {
            const int kp = ks * 8 + tid4;    // k-pair index (k = 2*kp)
            uint2 aP0[MF], aP1[MF], aP2[MF], aP3[MF];
            #pragma unroll
            for (int mt = 0; mt < MF; mt++) {
                const int r0 = mBase + mt * 16 + grp;
                aP0[mt] = Ab[(r0    ) * ROWW + kp    ];
                aP1[mt] = Ab[(r0 + 8) * ROWW + kp    ];
                aP2[mt] = Ab[(r0    ) * ROWW + kp + 4];
                aP3[mt] = Ab[(r0 + 8) * ROWW + kp + 4];
            }
            uint2 bP0[NF], bP1[NF];
            #pragma unroll
            for (int nt = 0; nt < NF; nt++) {
                const int n = nBase + nt * 8 + grp;
                bP0[nt] = Bb[n * ROWW + kp    ];
                bP1[nt] = Bb[n * ROWW + kp + 4];
            }
            #pragma unroll
            for (int mt = 0; mt < MF; mt++)
                #pragma unroll
                for (int nt = 0; nt < NF; nt++) {
                    // ah*bl + al*bh + ah*bh  (small terms first)
                    mma_bf16(acc[mt][nt],
                             aP0[mt].x, aP1[mt].x, aP2[mt].x, aP3[mt].x,
                             bP0[nt].y, bP1[nt].y);
                    mma_bf16(acc[mt][nt],
                             aP0[mt].y, aP1[mt].y, aP2[mt].y, aP3[mt].y,
                             bP0[nt].x, bP1[nt].x);
                    mma_bf16(acc[mt][nt],
                             aP0[mt].x, aP1[mt].x, aP2[mt].x, aP3[mt].x,
                             bP0[nt].x, bP1[nt].x);
                }
        }

        if (it + 1 < KT) sts_tile((it + 1) & 1);
        __syncthreads();
    }

    // epilogue
    #pragma unroll
    for (int mt = 0; mt < MF; mt++) {
        #pragma unroll
        for (int nt = 0; nt < NF; nt++) {
            #pragma unroll
            for (int r = 0; r < 4; r++) {
                const int m = m0 + mBase + mt * 16 + grp + ((r >= 2) ? 8 : 0);
                const int n = n0 + nBase + nt * 8 + tid4 * 2 + (r & 1);
                if (n < N) {
                    float v = acc[mt][nt][r];
                    if (EPI == 1) {
                        v += ep_bias[n];
                        v = fmaxf(v, 0.f) + log1pf(expf(-fabsf(v)));   // stable softplus
                        C[(size_t)m * N + n] = v;
                    } else if (EPI == 2) {
                        const int b = m >> 10, l = m & 1023;
                        const size_t o = (size_t)b * (size_t)N * LSEQ + (size_t)n * LSEQ + l;
                        C[o] = v + ep_res[o];
                    } else {
                        C[(size_t)m * N + n] = v;
                    }
                }
            }
        }
    }
}

// ---------------- depthwise causal conv (k=4) + bias + SiLU ----------------
__global__ void conv_silu_k(const float* __restrict__ xz, const float* __restrict__ cw,
                            const float* __restrict__ cb, float* __restrict__ xc)
{
    const int idx = blockIdx.x * blockDim.x + threadIdx.x;
    const int d = idx & (DINNER - 1);
    const int m = idx >> 11;
    const int l = m & (LSEQ - 1);

    float acc = cb[d];
    #pragma unroll
    for (int j = 0; j < 4; j++) {
        const int ll = l - 3 + j;
        if (ll >= 0)
            acc = fmaf(cw[d * 4 + j], xz[(size_t)(m - 3 + j) * NXZ + d], acc);
    }
    acc = acc / (1.f + __expf(-acc));
    xc[idx] = acc;
}

// ================= parallel chunked selective scan =================
__global__ void scan_part_k(const float* __restrict__ dt, const float* __restrict__ xc,
                            const float* __restrict__ xdbl, const float* __restrict__ A_log,
                            float* __restrict__ Ap_out, float* __restrict__ Hp_out)
{
    const int d = blockIdx.x * 128 + threadIdx.x;
    const int c = blockIdx.y;
    const int b = blockIdx.z;

    __shared__ float Bsh[CLEN][DSTATE];
    #pragma unroll
    for (int t = threadIdx.x; t < CLEN * DSTATE; t += 128) {
        const int l = t >> 4, i = t & 15;
        Bsh[l][i] = xdbl[(size_t)(b * LSEQ + c * CLEN + l) * NDBL + DTRANK + i];
    }
    __syncthreads();

    float a[DSTATE], Ap[DSTATE], h[DSTATE];
    #pragma unroll
    for (int s = 0; s < DSTATE; s++) {
        a[s]  = -expf(A_log[(size_t)d * DSTATE + s]);
        Ap[s] = 1.f;
        h[s]  = 0.f;
    }

    for (int l = 0; l < CLEN; l++) {
        const int m = b * LSEQ + c * CLEN + l;
        const float dtv = dt[(size_t)m * DINNER + d];
        const float xv  = xc[(size_t)m * DINNER + d];
        const float dtx = dtv * xv;
        #pragma unroll
        for (int s = 0; s < DSTATE; s++) {
            const float da = __expf(dtv * a[s]);
            Ap[s] *= da;
            h[s]   = fmaf(da, h[s], dtx * Bsh[l][s]);
        }
    }
    #pragma unroll
    for (int s = 0; s < DSTATE; s++) {
        const size_t o = ((size_t)((b * NCHUNK + c) * DSTATE + s) << 11) + d;
        Ap_out[o] = Ap[s];
        Hp_out[o] = h[s];
    }
}

__global__ void scan_mid_k(const float* __restrict__ Ap, const float* __restrict__ Hp,
                           float* __restrict__ hin)
{
    const int idx = blockIdx.x * 256 + threadIdx.x;
    const int d = idx & (DINNER - 1);
    const int s = (idx >> 11) & (DSTATE - 1);
    const int b = idx >> 15;

    float h = 0.f;
    #pragma unroll
    for (int c = 0; c < NCHUNK; c++) {
        const size_t o = ((size_t)((b * NCHUNK + c) * DSTATE + s) << 11) + d;
        hin[o] = h;
        h = fmaf(Ap[o], h, Hp[o]);
    }
}

__global__ void scan_out_k(const float* __restrict__ dt, const float* __restrict__ xc,
                           const float* __restrict__ xdbl, const float* __restrict__ xz,
                           const float* __restrict__ A_log, const float* __restrict__ Dp,
                           const float* __restrict__ hin, float* __restrict__ yout)
{
    const int d = blockIdx.x * 128 + threadIdx.x;
    const int c = blockIdx.y;
    const int b = blockIdx.z;

    __shared__ float Bsh[CLEN][DSTATE];
    __shared__ float Csh[CLEN][DSTATE];
    #pragma unroll
    for (int t = threadIdx.x; t < CLEN * 2 * DSTATE; t += 128) {
        const int l = t >> 5, i = t & 31;
        const float v = xdbl[(size_t)(b * LSEQ + c * CLEN + l) * NDBL + DTRANK + i];
        if (i < DSTATE) Bsh[l][i] = v;
        else            Csh[l][i - DSTATE] = v;
    }
    __syncthreads();

    float a[DSTATE], h[DSTATE];
    #pragma unroll
    for (int s = 0; s < DSTATE; s++) {
        a[s] = -expf(A_log[(size_t)d * DSTATE + s]);
        const size_t o = ((size_t)((b * NCHUNK + c) * DSTATE + s) << 11) + d;
        h[s] = hin[o];
    }
    const float Dd = Dp[d];

    for (int l = 0; l < CLEN; l++) {
        const int m = b * LSEQ + c * CLEN + l;
        const float dtv = dt[(size_t)m * DINNER + d];
        const float xv  = xc[(size_t)m * DINNER + d];
        const float dtx = dtv * xv;
        float y = 0.f;
        #pragma unroll
        for (int s = 0; s < DSTATE; s++) {
            const float da = __expf(dtv * a[s]);
            h[s] = fmaf(da, h[s], dtx * Bsh[l][s]);
            y    = fmaf(h[s], Csh[l][s], y);
        }
        const float zv = xz[(size_t)m * NXZ + DINNER + d];
        const float sz = zv / (1.f + __expf(-zv));
        yout[(size_t)m * DINNER + d] = (y + xv * Dd) * sz;
    }
}

// ---------------- driver ----------------
extern "C" void kernel_launch(void* const* d_in, const int* in_sizes, int n_in,
                              void* d_out, int out_size)
{
    const float* x    = (const float*)d_in[0];
    const float* lnw  = (const float*)d_in[1];
    const float* lnb  = (const float*)d_in[2];
    const float* win  = (const float*)d_in[3];
    const float* cw   = (const float*)d_in[4];
    const float* cb   = (const float*)d_in[5];
    const float* wx   = (const float*)d_in[6];
    const float* wdt  = (const float*)d_in[7];
    const float* bdt  = (const float*)d_in[8];
    const float* alog = (const float*)d_in[9];
    const float* Dp   = (const float*)d_in[10];
    const float* wout = (const float*)d_in[11];
    float* out = (float*)d_out;

    float *xn, *xz, *xc, *xdbl, *dtb, *yout, *ap, *hp, *hin;
    cudaGetSymbolAddress((void**)&xn,   g_xn);
    cudaGetSymbolAddress((void**)&xz,   g_xz);
    cudaGetSymbolAddress((void**)&xc,   g_xc);
    cudaGetSymbolAddress((void**)&xdbl, g_xdbl);
    cudaGetSymbolAddress((void**)&dtb,  g_dt);
    cudaGetSymbolAddress((void**)&yout, g_yout);
    cudaGetSymbolAddress((void**)&ap,   g_Ap);
    cudaGetSymbolAddress((void**)&hp,   g_Hp);
    cudaGetSymbolAddress((void**)&hin,  g_hin);

    // dynamic SMEM sizes (double buffer, uint2, ROWW=20)
    const int SM_128_128 = 2 * (128 + 128) * 20 * (int)sizeof(uint2);  // 81920
    const int SM_64_96   = 2 * (64 + 96)   * 20 * (int)sizeof(uint2);  // 51200

    cudaFuncSetAttribute(tgemm_k<128,128,2,4,0>, cudaFuncAttributeMaxDynamicSharedMemorySize, SM_128_128);
    cudaFuncSetAttribute(tgemm_k<128,128,2,4,1>, cudaFuncAttributeMaxDynamicSharedMemorySize, SM_128_128);
    cudaFuncSetAttribute(tgemm_k<128,128,2,4,2>, cudaFuncAttributeMaxDynamicSharedMemorySize, SM_128_128);
    cudaFuncSetAttribute(tgemm_k<64,96,2,4,0>,   cudaFuncAttributeMaxDynamicSharedMemorySize, SM_64_96);

    // 1. transpose (B,C,L) -> (B,L,C)
    transpose_k<<<dim3(LSEQ/32, DMODEL/32, BATCH), dim3(32, 8)>>>(x, xn);
    // 2. layernorm in place
    ln_k<<<MROWS, 256>>>(xn, lnw, lnb);
    // 3. in_proj (tensor bf16x3)
    tgemm_k<128,128,2,4,0><<<dim3(NXZ/128, MROWS/128), 256, SM_128_128>>>(
        xn, DMODEL, win, xz, MROWS, NXZ, DMODEL, nullptr, nullptr);
    // 4. depthwise conv + silu
    conv_silu_k<<<(MROWS*DINNER)/256, 256>>>(xz, cw, cb, xc);
    // 5. x_proj
    tgemm_k<64,96,2,4,0><<<dim3(1, MROWS/64), 256, SM_64_96>>>(
        xc, DINNER, wx, xdbl, MROWS, NDBL, DINNER, nullptr, nullptr);
    // 6. dt_proj + softplus
    tgemm_k<128,128,2,4,1><<<dim3(DINNER/128, MROWS/128), 256, SM_128_128>>>(
        xdbl, NDBL, wdt, dtb, MROWS, DINNER, DTRANK, bdt, nullptr);
    // 7-9. parallel chunked selective scan
    scan_part_k<<<dim3(DINNER/128, NCHUNK, BATCH), 128>>>(dtb, xc, xdbl, alog, ap, hp);
    scan_mid_k<<<(BATCH*DSTATE*DINNER)/256, 256>>>(ap, hp, hin);
    scan_out_k<<<dim3(DINNER/128, NCHUNK, BATCH), 128>>>(dtb, xc, xdbl, xz, alog, Dp, hin, yout);
    // 10. out_proj + transpose-store + residual
    tgemm_k<128,128,2,4,2><<<dim3(DMODEL/128, MROWS/128), 256, SM_128_128>>>(
        yout, DINNER, wout, out, MROWS, DMODEL, DINNER, nullptr, x);
}

// round 16
// speedup vs baseline: 1.1221x; 1.1221x over previous
#include <cuda_runtime.h>
#include <cuda_bf16.h>
#include <math.h>
#include <stdint.h>

// ---------------- problem constants ----------------
#define BATCH   2
#define LSEQ    1024
#define DMODEL  1024
#define DINNER  2048
#define DSTATE  16
#define DTRANK  64
#define NXZ     (2*DINNER)           // 4096
#define NDBL    (DTRANK + 2*DSTATE)  // 96
#define MROWS   (BATCH*LSEQ)         // 2048
#define NCHUNK  16
#define CLEN    64                   // LSEQ / NCHUNK

// ---------------- scratch (static device memory; no allocation) ----------------
__device__ float g_xn  [MROWS * DMODEL];
__device__ float g_xz  [MROWS * NXZ];
__device__ float g_xc  [MROWS * DINNER];
__device__ float g_xdbl[MROWS * NDBL];
__device__ float g_dt  [MROWS * DINNER];
__device__ float g_Ap  [BATCH * NCHUNK * DSTATE * DINNER];
__device__ float g_Hp  [BATCH * NCHUNK * DSTATE * DINNER];
__device__ float g_hin [BATCH * NCHUNK * DSTATE * DINNER];

// bf16 hi/lo planes (weights converted per call; activations fused in producers)
__device__ __nv_bfloat16 g_winH[NXZ*DMODEL],    g_winL[NXZ*DMODEL];
__device__ __nv_bfloat16 g_wxH [NDBL*DINNER],   g_wxL [NDBL*DINNER];
__device__ __nv_bfloat16 g_wdtH[DINNER*DTRANK], g_wdtL[DINNER*DTRANK];
__device__ __nv_bfloat16 g_woutH[DMODEL*DINNER],g_woutL[DMODEL*DINNER];
__device__ __nv_bfloat16 g_xnH[MROWS*DMODEL],   g_xnL[MROWS*DMODEL];
__device__ __nv_bfloat16 g_xcH[MROWS*DINNER],   g_xcL[MROWS*DINNER];
__device__ __nv_bfloat16 g_dtAH[MROWS*DTRANK],  g_dtAL[MROWS*DTRANK];
__device__ __nv_bfloat16 g_yH [MROWS*DINNER],   g_yL [MROWS*DINNER];

// ---------------- transpose (B,C,L) -> (B,L,C) ----------------
__global__ void transpose_k(const float* __restrict__ x, float* __restrict__ xt)
{
    __shared__ float t[32][33];
    const int b  = blockIdx.z;
    const int c0 = blockIdx.y * 32;
    const int l0 = blockIdx.x * 32;
    #pragma unroll
    for (int i = threadIdx.y; i < 32; i += 8)
        t[i][threadIdx.x] = x[(size_t)b*DMODEL*LSEQ + (size_t)(c0+i)*LSEQ + l0 + threadIdx.x];
    __syncthreads();
    #pragma unroll
    for (int i = threadIdx.y; i < 32; i += 8)
        xt[(size_t)b*LSEQ*DMODEL + (size_t)(l0+i)*DMODEL + c0 + threadIdx.x] = t[threadIdx.x][i];
}

// ---------------- layernorm -> bf16 hi/lo planes ----------------
__global__ void ln_k(const float* __restrict__ xn, const float* __restrict__ w,
                     const float* __restrict__ bsh,
                     __nv_bfloat16* __restrict__ oh, __nv_bfloat16* __restrict__ ol)
{
    const int m = blockIdx.x;
    const float* row = xn + (size_t)m * DMODEL;
    __shared__ float sm[DMODEL];
    __shared__ float rs[8], rs2[8];
    __shared__ float s_mu, s_rstd;
    const int tid = threadIdx.x;   // 256

    float s = 0.f, s2 = 0.f;
    #pragma unroll
    for (int i = tid; i < DMODEL; i += 256) {
        float v = row[i];
        sm[i] = v;
        s += v;
        s2 = fmaf(v, v, s2);
    }
    #pragma unroll
    for (int o = 16; o > 0; o >>= 1) {
        s  += __shfl_xor_sync(0xffffffffu, s,  o);
        s2 += __shfl_xor_sync(0xffffffffu, s2, o);
    }
    if ((tid & 31) == 0) { rs[tid >> 5] = s; rs2[tid >> 5] = s2; }
    __syncthreads();
    if (tid == 0) {
        float S = 0.f, S2 = 0.f;
        #pragma unroll
        for (int i = 0; i < 8; i++) { S += rs[i]; S2 += rs2[i]; }
        float mu  = S * (1.0f / DMODEL);
        float var = S2 * (1.0f / DMODEL) - mu * mu;
        s_mu = mu;
        s_rstd = rsqrtf(var + 1e-5f);
    }
    __syncthreads();
    const float mu = s_mu, r = s_rstd;
    #pragma unroll
    for (int i = tid; i < DMODEL; i += 256) {
        const float v = (sm[i] - mu) * r * w[i] + bsh[i];
        const __nv_bfloat16 h = __float2bfloat16(v);
        oh[(size_t)m * DMODEL + i] = h;
        ol[(size_t)m * DMODEL + i] = __float2bfloat16(v - __bfloat162float(h));
    }
}

// ---------------- fp32 -> bf16 hi/lo plane converter (weights) ----------------
__global__ void cvt_k(const float4* __restrict__ s, __nv_bfloat162* __restrict__ h2,
                      __nv_bfloat162* __restrict__ l2, int n4)
{
    const int i = blockIdx.x * 256 + threadIdx.x;
    if (i < n4) {
        float4 v = s[i];
        __nv_bfloat162 h0 = __floats2bfloat162_rn(v.x, v.y);
        __nv_bfloat162 h1 = __floats2bfloat162_rn(v.z, v.w);
        __nv_bfloat162 l0 = __floats2bfloat162_rn(v.x - __bfloat162float(h0.x),
                                                  v.y - __bfloat162float(h0.y));
        __nv_bfloat162 l1 = __floats2bfloat162_rn(v.z - __bfloat162float(h1.x),
                                                  v.w - __bfloat162float(h1.y));
        h2[2*i] = h0; h2[2*i+1] = h1;
        l2[2*i] = l0; l2[2*i+1] = l1;
    }
}

// ---------------- asm helpers ----------------
__device__ __forceinline__ uint32_t smem_u32(const void* p) {
    uint32_t a;
    asm("{ .reg .u64 t; cvta.to.shared.u64 t, %1; cvt.u32.u64 %0, t; }" : "=r"(a) : "l"(p));
    return a;
}
__device__ __forceinline__ void cp16(uint32_t dst, const void* src) {
    asm volatile("cp.async.cg.shared.global [%0], [%1], 16;" :: "r"(dst), "l"(src));
}
#define CP_COMMIT() asm volatile("cp.async.commit_group;" ::: "memory")
#define CP_WAIT0()  asm volatile("cp.async.wait_group 0;" ::: "memory")
__device__ __forceinline__ uint32_t lds32(uint32_t a) {
    uint32_t v;
    asm volatile("ld.shared.b32 %0, [%1];" : "=r"(v) : "r"(a));
    return v;
}
__device__ __forceinline__ void mma_bf16(float* c,
    uint32_t a0, uint32_t a1, uint32_t a2, uint32_t a3,
    uint32_t b0, uint32_t b1)
{
    asm volatile(
        "mma.sync.aligned.m16n8k16.row.col.f32.bf16.bf16.f32 "
        "{%0,%1,%2,%3}, {%4,%5,%6,%7}, {%8,%9}, {%0,%1,%2,%3};"
        : "+f"(c[0]), "+f"(c[1]), "+f"(c[2]), "+f"(c[3])
        : "r"(a0), "r"(a1), "r"(a2), "r"(a3), "r"(b0), "r"(b1));
}

// ---------------- bf16x3 plane GEMM, cp.async double buffer ----------------
// C[m][n] = sum_k A[m][k]*W[n][k]; A,W given as bf16 hi/lo planes, lda = ldb = K.
// EPI: 0 plain, 1 softplus(acc+bias[n]), 2 transpose+residual to d_out,
//      3 plain fp32 + bf16 hi/lo planes for columns n < DTRANK (dt_raw).
// All launched shapes tile exactly (no bounds predicates on loads).
template<int BM, int BN, int WM, int WN, int EPI>
__global__ void __launch_bounds__(256, 2)
pgemm_k(const __nv_bfloat16* __restrict__ Ah, const __nv_bfloat16* __restrict__ Al,
        const __nv_bfloat16* __restrict__ Bh, const __nv_bfloat16* __restrict__ Bl,
        float* __restrict__ C, int M, int N, int K,
        const float* __restrict__ ep_bias, const float* __restrict__ ep_res,
        __nv_bfloat16* __restrict__ ep_dtH, __nv_bfloat16* __restrict__ ep_dtL)
{
    constexpr int BK  = 32;
    constexpr int RB  = 80;                 // smem row bytes: 64 data + 16 pad (20 words)
    constexpr int PLA = BM * RB;
    constexpr int PLB = BN * RB;
    constexpr int STG = 2 * PLA + 2 * PLB;  // Ahi|Alo|Bhi|Blo
    constexpr int WTM = BM / WM, WTN = BN / WN;
    constexpr int MF  = WTM / 16, NF = WTN / 8;
    constexpr int ACH = BM * 8;             // 16B chunks per stage (A: 4/row x 2 planes)
    constexpr int BCH = BN * 8;

    extern __shared__ char smem[];
    const uint32_t s0 = smem_u32(smem);

    const int tid  = threadIdx.x;
    const int warp = tid >> 5, lane = tid & 31;
    const int grp  = lane >> 2, tid4 = lane & 3;
    const int warpM = warp % WM, warpN = warp / WM;
    const int mBase = warpM * WTM, nBase = warpN * WTN;
    const int m0 = blockIdx.y * BM, n0 = blockIdx.x * BN;

    float acc[MF][NF][4];
    #pragma unroll
    for (int i = 0; i < MF; i++)
        #pragma unroll
        for (int j = 0; j < NF; j++)
            #pragma unroll
            for (int r = 0; r < 4; r++) acc[i][j][r] = 0.f;

    auto load_stage = [&](int st, int k0) {
        const uint32_t dA = s0 + st * STG;
        for (int t = tid; t < ACH; t += 256) {
            const int row = t >> 3, c = t & 7, pl = c >> 2, ch = c & 3;
            const __nv_bfloat16* src = (pl ? Al : Ah)
                + (size_t)(m0 + row) * K + k0 + ch * 8;
            cp16(dA + pl * PLA + row * RB + ch * 16, src);
        }
        const uint32_t dB = s0 + st * STG + 2 * PLA;
        for (int t = tid; t < BCH; t += 256) {
            const int row = t >> 3, c = t & 7, pl = c >> 2, ch = c & 3;
            const __nv_bfloat16* src = (pl ? Bl : Bh)
                + (size_t)(n0 + row) * K + k0 + ch * 8;
            cp16(dB + pl * PLB + row * RB + ch * 16, src);
        }
    };

    const int KT = K / BK;
    load_stage(0, 0);
    CP_COMMIT();

    for (int it = 0; it < KT; it++) {
        CP_WAIT0();
        __syncthreads();
        if (it + 1 < KT) { load_stage((it + 1) & 1, (it + 1) * BK); CP_COMMIT(); }

        const uint32_t sA = s0 + (it & 1) * STG;
        const uint32_t sB = sA + 2 * PLA;

        #pragma unroll
        for (int ks = 0; ks < 2; ks++) {
            const int kw = (ks * 8 + tid4) * 4;   // byte offset of k-pair word
            uint32_t ah[MF][4], al_[MF][4];
            #pragma unroll
            for (int mt = 0; mt < MF; mt++) {
                const uint32_t a0 = sA + (mBase + mt * 16 + grp) * RB + kw;
                ah[mt][0]  = lds32(a0);
                ah[mt][1]  = lds32(a0 + 8 * RB);
                ah[mt][2]  = lds32(a0 + 16);
                ah[mt][3]  = lds32(a0 + 8 * RB + 16);
                const uint32_t a1 = a0 + PLA;
                al_[mt][0] = lds32(a1);
                al_[mt][1] = lds32(a1 + 8 * RB);
                al_[mt][2] = lds32(a1 + 16);
                al_[mt][3] = lds32(a1 + 8 * RB + 16);
            }
            uint32_t bh[NF][2], bl_[NF][2];
            #pragma unroll
            for (int nt = 0; nt < NF; nt++) {
                const uint32_t b0 = sB + (nBase + nt * 8 + grp) * RB + kw;
                bh[nt][0]  = lds32(b0);
                bh[nt][1]  = lds32(b0 + 16);
                const uint32_t b1 = b0 + PLB;
                bl_[nt][0] = lds32(b1);
                bl_[nt][1] = lds32(b1 + 16);
            }
            #pragma unroll
            for (int mt = 0; mt < MF; mt++)
                #pragma unroll
                for (int nt = 0; nt < NF; nt++) {
                    mma_bf16(acc[mt][nt], ah[mt][0], ah[mt][1], ah[mt][2], ah[mt][3],
                             bl_[nt][0], bl_[nt][1]);
                    mma_bf16(acc[mt][nt], al_[mt][0], al_[mt][1], al_[mt][2], al_[mt][3],
                             bh[nt][0], bh[nt][1]);
                    mma_bf16(acc[mt][nt], ah[mt][0], ah[mt][1], ah[mt][2], ah[mt][3],
                             bh[nt][0], bh[nt][1]);
                }
        }
        __syncthreads();
    }

    // epilogue
    #pragma unroll
    for (int mt = 0; mt < MF; mt++) {
        #pragma unroll
        for (int nt = 0; nt < NF; nt++) {
            #pragma unroll
            for (int r = 0; r < 4; r++) {
                const int m = m0 + mBase + mt * 16 + grp + ((r >= 2) ? 8 : 0);
                const int n = n0 + nBase + nt * 8 + tid4 * 2 + (r & 1);
                if (n < N) {
                    float v = acc[mt][nt][r];
                    if (EPI == 1) {
                        v += ep_bias[n];
                        v = fmaxf(v, 0.f) + log1pf(expf(-fabsf(v)));   // stable softplus
                        C[(size_t)m * N + n] = v;
                    } else if (EPI == 2) {
                        const int b = m >> 10, l = m & 1023;
                        const size_t o = (size_t)b * (size_t)N * LSEQ + (size_t)n * LSEQ + l;
                        C[o] = v + ep_res[o];
                    } else if (EPI == 3) {
                        C[(size_t)m * N + n] = v;
                        if (n < DTRANK) {
                            const __nv_bfloat16 h = __float2bfloat16(v);
                            ep_dtH[(size_t)m * DTRANK + n] = h;
                            ep_dtL[(size_t)m * DTRANK + n] =
                                __float2bfloat16(v - __bfloat162float(h));
                        }
                    } else {
                        C[(size_t)m * N + n] = v;
                    }
                }
            }
        }
    }
}

// ---------------- depthwise causal conv (k=4) + bias + SiLU (+ planes) ----------------
__global__ void conv_silu_k(const float* __restrict__ xz, const float* __restrict__ cw,
                            const float* __restrict__ cb, float* __restrict__ xc,
                            __nv_bfloat16* __restrict__ xcH, __nv_bfloat16* __restrict__ xcL)
{
    const int idx = blockIdx.x * blockDim.x + threadIdx.x;
    const int d = idx & (DINNER - 1);
    const int m = idx >> 11;
    const int l = m & (LSEQ - 1);

    float acc = cb[d];
    #pragma unroll
    for (int j = 0; j < 4; j++) {
        const int ll = l - 3 + j;
        if (ll >= 0)
            acc = fmaf(cw[d * 4 + j], xz[(size_t)(m - 3 + j) * NXZ + d], acc);
    }
    acc = acc / (1.f + __expf(-acc));
    xc[idx] = acc;
    const __nv_bfloat16 h = __float2bfloat16(acc);
    xcH[idx] = h;
    xcL[idx] = __float2bfloat16(acc - __bfloat162float(h));
}

// ================= parallel chunked selective scan =================
__global__ void scan_part_k(const float* __restrict__ dt, const float* __restrict__ xc,
                            const float* __restrict__ xdbl, const float* __restrict__ A_log,
                            float* __restrict__ Ap_out, float* __restrict__ Hp_out)
{
    const int d = blockIdx.x * 128 + threadIdx.x;
    const int c = blockIdx.y;
    const int b = blockIdx.z;

    __shared__ float Bsh[CLEN][DSTATE];
    #pragma unroll
    for (int t = threadIdx.x; t < CLEN * DSTATE; t += 128) {
        const int l = t >> 4, i = t & 15;
        Bsh[l][i] = xdbl[(size_t)(b * LSEQ + c * CLEN + l) * NDBL + DTRANK + i];
    }
    __syncthreads();

    float a[DSTATE], Ap[DSTATE], h[DSTATE];
    #pragma unroll
    for (int s = 0; s < DSTATE; s++) {
        a[s]  = -expf(A_log[(size_t)d * DSTATE + s]);
        Ap[s] = 1.f;
        h[s]  = 0.f;
    }

    for (int l = 0; l < CLEN; l++) {
        const int m = b * LSEQ + c * CLEN + l;
        const float dtv = dt[(size_t)m * DINNER + d];
        const float xv  = xc[(size_t)m * DINNER + d];
        const float dtx = dtv * xv;
        #pragma unroll
        for (int s = 0; s < DSTATE; s++) {
            const float da = __expf(dtv * a[s]);
            Ap[s] *= da;
            h[s]   = fmaf(da, h[s], dtx * Bsh[l][s]);
        }
    }
    #pragma unroll
    for (int s = 0; s < DSTATE; s++) {
        const size_t o = ((size_t)((b * NCHUNK + c) * DSTATE + s) << 11) + d;
        Ap_out[o] = Ap[s];
        Hp_out[o] = h[s];
    }
}

__global__ void scan_mid_k(const float* __restrict__ Ap, const float* __restrict__ Hp,
                           float* __restrict__ hin)
{
    const int idx = blockIdx.x * 256 + threadIdx.x;
    const int d = idx & (DINNER - 1);
    const int s = (idx >> 11) & (DSTATE - 1);
    const int b = idx >> 15;

    float h = 0.f;
    #pragma unroll
    for (int c = 0; c < NCHUNK; c++) {
        const size_t o = ((size_t)((b * NCHUNK + c) * DSTATE + s) << 11) + d;
        hin[o] = h;
        h = fmaf(Ap[o], h, Hp[o]);
    }
}

__global__ void scan_out_k(const float* __restrict__ dt, const float* __restrict__ xc,
                           const float* __restrict__ xdbl, const float* __restrict__ xz,
                           const float* __restrict__ A_log, const float* __restrict__ Dp,
                           const float* __restrict__ hin,
                           __nv_bfloat16* __restrict__ yH, __nv_bfloat16* __restrict__ yL)
{
    const int d = blockIdx.x * 128 + threadIdx.x;
    const int c = blockIdx.y;
    const int b = blockIdx.z;

    __shared__ float Bsh[CLEN][DSTATE];
    __shared__ float Csh[CLEN][DSTATE];
    #pragma unroll
    for (int t = threadIdx.x; t < CLEN * 2 * DSTATE; t += 128) {
        const int l = t >> 5, i = t & 31;
        const float v = xdbl[(size_t)(b * LSEQ + c * CLEN + l) * NDBL + DTRANK + i];
        if (i < DSTATE) Bsh[l][i] = v;
        else            Csh[l][i - DSTATE] = v;
    }
    __syncthreads();

    float a[DSTATE], h[DSTATE];
    #pragma unroll
    for (int s = 0; s < DSTATE; s++) {
        a[s] = -expf(A_log[(size_t)d * DSTATE + s]);
        const size_t o = ((size_t)((b * NCHUNK + c) * DSTATE + s) << 11) + d;
        h[s] = hin[o];
    }
    const float Dd = Dp[d];

    for (int l = 0; l < CLEN; l++) {
        const int m = b * LSEQ + c * CLEN + l;
        const float dtv = dt[(size_t)m * DINNER + d];
        const float xv  = xc[(size_t)m * DINNER + d];
        const float dtx = dtv * xv;
        float y = 0.f;
        #pragma unroll
        for (int s = 0; s < DSTATE; s++) {
            const float da = __expf(dtv * a[s]);
            h[s] = fmaf(da, h[s], dtx * Bsh[l][s]);
            y    = fmaf(h[s], Csh[l][s], y);
        }
        const float zv = xz[(size_t)m * NXZ + DINNER + d];
        const float sz = zv / (1.f + __expf(-zv));
        const float yo = (y + xv * Dd) * sz;
        const __nv_bfloat16 hh = __float2bfloat16(yo);
        yH[(size_t)m * DINNER + d] = hh;
        yL[(size_t)m * DINNER + d] = __float2bfloat16(yo - __bfloat162float(hh));
    }
}

// ---------------- driver ----------------
extern "C" void kernel_launch(void* const* d_in, const int* in_sizes, int n_in,
                              void* d_out, int out_size)
{
    const float* x    = (const float*)d_in[0];
    const float* lnw  = (const float*)d_in[1];
    const float* lnb  = (const float*)d_in[2];
    const float* win  = (const float*)d_in[3];
    const float* cw   = (const float*)d_in[4];
    const float* cb   = (const float*)d_in[5];
    const float* wx   = (const float*)d_in[6];
    const float* wdt  = (const float*)d_in[7];
    const float* bdt  = (const float*)d_in[8];
    const float* alog = (const float*)d_in[9];
    const float* Dp   = (const float*)d_in[10];
    const float* wout = (const float*)d_in[11];
    float* out = (float*)d_out;

    float *xn, *xz, *xc, *xdbl, *dtb, *ap, *hp, *hin;
    cudaGetSymbolAddress((void**)&xn,   g_xn);
    cudaGetSymbolAddress((void**)&xz,   g_xz);
    cudaGetSymbolAddress((void**)&xc,   g_xc);
    cudaGetSymbolAddress((void**)&xdbl, g_xdbl);
    cudaGetSymbolAddress((void**)&dtb,  g_dt);
    cudaGetSymbolAddress((void**)&ap,   g_Ap);
    cudaGetSymbolAddress((void**)&hp,   g_Hp);
    cudaGetSymbolAddress((void**)&hin,  g_hin);

    __nv_bfloat16 *winH,*winL,*wxH,*wxL,*wdtH,*wdtL,*woutH,*woutL;
    __nv_bfloat16 *xnH,*xnL,*xcH,*xcL,*dtAH,*dtAL,*yH,*yL;
    cudaGetSymbolAddress((void**)&winH, g_winH);  cudaGetSymbolAddress((void**)&winL, g_winL);
    cudaGetSymbolAddress((void**)&wxH,  g_wxH);   cudaGetSymbolAddress((void**)&wxL,  g_wxL);
    cudaGetSymbolAddress((void**)&wdtH, g_wdtH);  cudaGetSymbolAddress((void**)&wdtL, g_wdtL);
    cudaGetSymbolAddress((void**)&woutH,g_woutH); cudaGetSymbolAddress((void**)&woutL,g_woutL);
    cudaGetSymbolAddress((void**)&xnH,  g_xnH);   cudaGetSymbolAddress((void**)&xnL,  g_xnL);
    cudaGetSymbolAddress((void**)&xcH,  g_xcH);   cudaGetSymbolAddress((void**)&xcL,  g_xcL);
    cudaGetSymbolAddress((void**)&dtAH, g_dtAH);  cudaGetSymbolAddress((void**)&dtAL, g_dtAL);
    cudaGetSymbolAddress((void**)&yH,   g_yH);    cudaGetSymbolAddress((void**)&yL,   g_yL);

    // dynamic SMEM (2 stages x (2*BM + 2*BN) rows x 80B)
    const int SM_128_128 = 2 * 2 * (128 + 128) * 80;  // 81920
    const int SM_64_96   = 2 * 2 * (64 + 96)   * 80;  // 51200
    cudaFuncSetAttribute(pgemm_k<128,128,2,4,0>, cudaFuncAttributeMaxDynamicSharedMemorySize, SM_128_128);
    cudaFuncSetAttribute(pgemm_k<128,128,2,4,1>, cudaFuncAttributeMaxDynamicSharedMemorySize, SM_128_128);
    cudaFuncSetAttribute(pgemm_k<128,128,2,4,2>, cudaFuncAttributeMaxDynamicSharedMemorySize, SM_128_128);
    cudaFuncSetAttribute(pgemm_k<64,96,2,4,3>,   cudaFuncAttributeMaxDynamicSharedMemorySize, SM_64_96);

    // 0. weight planes (per call; deterministic)
    cvt_k<<<(NXZ*DMODEL/4 + 255)/256, 256>>>((const float4*)win,  (__nv_bfloat162*)winH,  (__nv_bfloat162*)winL,  NXZ*DMODEL/4);
    cvt_k<<<(NDBL*DINNER/4 + 255)/256, 256>>>((const float4*)wx,  (__nv_bfloat162*)wxH,   (__nv_bfloat162*)wxL,   NDBL*DINNER/4);
    cvt_k<<<(DINNER*DTRANK/4 + 255)/256, 256>>>((const float4*)wdt,(__nv_bfloat162*)wdtH, (__nv_bfloat162*)wdtL,  DINNER*DTRANK/4);
    cvt_k<<<(DMODEL*DINNER/4 + 255)/256, 256>>>((const float4*)wout,(__nv_bfloat162*)woutH,(__nv_bfloat162*)woutL, DMODEL*DINNER/4);

    // 1. transpose (B,C,L) -> (B,L,C)
    transpose_k<<<dim3(LSEQ/32, DMODEL/32, BATCH), dim3(32, 8)>>>(x, xn);
    // 2. layernorm -> xn planes
    ln_k<<<MROWS, 256>>>(xn, lnw, lnb, xnH, xnL);
    // 3. in_proj: (2048x1024) x (4096x1024)^T -> xz
    pgemm_k<128,128,2,4,0><<<dim3(NXZ/128, MROWS/128), 256, SM_128_128>>>(
        xnH, xnL, winH, winL, xz, MROWS, NXZ, DMODEL, nullptr, nullptr, nullptr, nullptr);
    // 4. depthwise conv + silu -> xc fp32 + planes
    conv_silu_k<<<(MROWS*DINNER)/256, 256>>>(xz, cw, cb, xc, xcH, xcL);
    // 5. x_proj -> xdbl fp32 (+ dt_raw planes for cols < 64)
    pgemm_k<64,96,2,4,3><<<dim3(1, MROWS/64), 256, SM_64_96>>>(
        xcH, xcL, wxH, wxL, xdbl, MROWS, NDBL, DINNER, nullptr, nullptr, dtAH, dtAL);
    // 6. dt_proj + softplus -> dt fp32
    pgemm_k<128,128,2,4,1><<<dim3(DINNER/128, MROWS/128), 256, SM_128_128>>>(
        dtAH, dtAL, wdtH, wdtL, dtb, MROWS, DINNER, DTRANK, bdt, nullptr, nullptr, nullptr);
    // 7-9. parallel chunked selective scan -> yout planes
    scan_part_k<<<dim3(DINNER/128, NCHUNK, BATCH), 128>>>(dtb, xc, xdbl, alog, ap, hp);
    scan_mid_k<<<(BATCH*DSTATE*DINNER)/256, 256>>>(ap, hp, hin);
    scan_out_k<<<dim3(DINNER/128, NCHUNK, BATCH), 128>>>(dtb, xc, xdbl, xz, alog, Dp, hin, yH, yL);
    // 10. out_proj + transpose-store + residual
    pgemm_k<128,128,2,4,2><<<dim3(DMODEL/128, MROWS/128), 256, SM_128_128>>>(
        yH, yL, woutH, woutL, out, MROWS, DMODEL, DINNER, nullptr, x, nullptr, nullptr);
}

// round 17
// speedup vs baseline: 1.2242x; 1.0910x over previous
#include <cuda_runtime.h>
#include <cuda_bf16.h>
#include <math.h>
#include <stdint.h>

// ---------------- problem constants ----------------
#define BATCH   2
#define LSEQ    1024
#define DMODEL  1024
#define DINNER  2048
#define DSTATE  16
#define DTRANK  64
#define NXZ     (2*DINNER)           // 4096
#define NDBL    (DTRANK + 2*DSTATE)  // 96
#define MROWS   (BATCH*LSEQ)         // 2048
#define NCHUNK  16
#define CLEN    64                   // LSEQ / NCHUNK
#define XPSK    8                    // x_proj split-K factor

// ---------------- scratch (static device memory; no allocation) ----------------
__device__ float g_xn  [MROWS * DMODEL];
__device__ float g_xz  [MROWS * NXZ];
__device__ float g_xc  [MROWS * DINNER];
__device__ float g_xdbl[MROWS * NDBL];
__device__ float g_dt  [MROWS * DINNER];
__device__ float g_Ap  [BATCH * NCHUNK * DSTATE * DINNER];
__device__ float g_Hp  [BATCH * NCHUNK * DSTATE * DINNER];
__device__ float g_hin [BATCH * NCHUNK * DSTATE * DINNER];
__device__ float g_part[XPSK * MROWS * NDBL];               // split-K partials (6.3 MB)

// bf16 hi/lo planes (weights converted per call; activations fused in producers)
__device__ __nv_bfloat16 g_winH[NXZ*DMODEL],    g_winL[NXZ*DMODEL];
__device__ __nv_bfloat16 g_wxH [NDBL*DINNER],   g_wxL [NDBL*DINNER];
__device__ __nv_bfloat16 g_wdtH[DINNER*DTRANK], g_wdtL[DINNER*DTRANK];
__device__ __nv_bfloat16 g_woutH[DMODEL*DINNER],g_woutL[DMODEL*DINNER];
__device__ __nv_bfloat16 g_xnH[MROWS*DMODEL],   g_xnL[MROWS*DMODEL];
__device__ __nv_bfloat16 g_xcH[MROWS*DINNER],   g_xcL[MROWS*DINNER];
__device__ __nv_bfloat16 g_dtAH[MROWS*DTRANK],  g_dtAL[MROWS*DTRANK];
__device__ __nv_bfloat16 g_yH [MROWS*DINNER],   g_yL [MROWS*DINNER];

// ---------------- transpose (B,C,L) -> (B,L,C) ----------------
__global__ void transpose_k(const float* __restrict__ x, float* __restrict__ xt)
{
    __shared__ float t[32][33];
    const int b  = blockIdx.z;
    const int c0 = blockIdx.y * 32;
    const int l0 = blockIdx.x * 32;
    #pragma unroll
    for (int i = threadIdx.y; i < 32; i += 8)
        t[i][threadIdx.x] = x[(size_t)b*DMODEL*LSEQ + (size_t)(c0+i)*LSEQ + l0 + threadIdx.x];
    __syncthreads();
    #pragma unroll
    for (int i = threadIdx.y; i < 32; i += 8)
        xt[(size_t)b*LSEQ*DMODEL + (size_t)(l0+i)*DMODEL + c0 + threadIdx.x] = t[threadIdx.x][i];
}

// ---------------- layernorm -> bf16 hi/lo planes ----------------
__global__ void ln_k(const float* __restrict__ xn, const float* __restrict__ w,
                     const float* __restrict__ bsh,
                     __nv_bfloat16* __restrict__ oh, __nv_bfloat16* __restrict__ ol)
{
    const int m = blockIdx.x;
    const float* row = xn + (size_t)m * DMODEL;
    __shared__ float sm[DMODEL];
    __shared__ float rs[8], rs2[8];
    __shared__ float s_mu, s_rstd;
    const int tid = threadIdx.x;   // 256

    float s = 0.f, s2 = 0.f;
    #pragma unroll
    for (int i = tid; i < DMODEL; i += 256) {
        float v = row[i];
        sm[i] = v;
        s += v;
        s2 = fmaf(v, v, s2);
    }
    #pragma unroll
    for (int o = 16; o > 0; o >>= 1) {
        s  += __shfl_xor_sync(0xffffffffu, s,  o);
        s2 += __shfl_xor_sync(0xffffffffu, s2, o);
    }
    if ((tid & 31) == 0) { rs[tid >> 5] = s; rs2[tid >> 5] = s2; }
    __syncthreads();
    if (tid == 0) {
        float S = 0.f, S2 = 0.f;
        #pragma unroll
        for (int i = 0; i < 8; i++) { S += rs[i]; S2 += rs2[i]; }
        float mu  = S * (1.0f / DMODEL);
        float var = S2 * (1.0f / DMODEL) - mu * mu;
        s_mu = mu;
        s_rstd = rsqrtf(var + 1e-5f);
    }
    __syncthreads();
    const float mu = s_mu, r = s_rstd;
    #pragma unroll
    for (int i = tid; i < DMODEL; i += 256) {
        const float v = (sm[i] - mu) * r * w[i] + bsh[i];
        const __nv_bfloat16 h = __float2bfloat16(v);
        oh[(size_t)m * DMODEL + i] = h;
        ol[(size_t)m * DMODEL + i] = __float2bfloat16(v - __bfloat162float(h));
    }
}

// ---------------- fp32 -> bf16 hi/lo plane converter (weights) ----------------
__global__ void cvt_k(const float4* __restrict__ s, __nv_bfloat162* __restrict__ h2,
                      __nv_bfloat162* __restrict__ l2, int n4)
{
    const int i = blockIdx.x * 256 + threadIdx.x;
    if (i < n4) {
        float4 v = s[i];
        __nv_bfloat162 h0 = __floats2bfloat162_rn(v.x, v.y);
        __nv_bfloat162 h1 = __floats2bfloat162_rn(v.z, v.w);
        __nv_bfloat162 l0 = __floats2bfloat162_rn(v.x - __bfloat162float(h0.x),
                                                  v.y - __bfloat162float(h0.y));
        __nv_bfloat162 l1 = __floats2bfloat162_rn(v.z - __bfloat162float(h1.x),
                                                  v.w - __bfloat162float(h1.y));
        h2[2*i] = h0; h2[2*i+1] = h1;
        l2[2*i] = l0; l2[2*i+1] = l1;
    }
}

// ---------------- asm helpers ----------------
__device__ __forceinline__ uint32_t smem_u32(const void* p) {
    uint32_t a;
    asm("{ .reg .u64 t; cvta.to.shared.u64 t, %1; cvt.u32.u64 %0, t; }" : "=r"(a) : "l"(p));
    return a;
}
__device__ __forceinline__ void cp16(uint32_t dst, const void* src) {
    asm volatile("cp.async.cg.shared.global [%0], [%1], 16;" :: "r"(dst), "l"(src));
}
#define CP_COMMIT() asm volatile("cp.async.commit_group;" ::: "memory")
#define CP_WAIT0()  asm volatile("cp.async.wait_group 0;" ::: "memory")
__device__ __forceinline__ uint32_t lds32(uint32_t a) {
    uint32_t v;
    asm volatile("ld.shared.b32 %0, [%1];" : "=r"(v) : "r"(a));
    return v;
}
__device__ __forceinline__ void mma_bf16(float* c,
    uint32_t a0, uint32_t a1, uint32_t a2, uint32_t a3,
    uint32_t b0, uint32_t b1)
{
    asm volatile(
        "mma.sync.aligned.m16n8k16.row.col.f32.bf16.bf16.f32 "
        "{%0,%1,%2,%3}, {%4,%5,%6,%7}, {%8,%9}, {%0,%1,%2,%3};"
        : "+f"(c[0]), "+f"(c[1]), "+f"(c[2]), "+f"(c[3])
        : "r"(a0), "r"(a1), "r"(a2), "r"(a3), "r"(b0), "r"(b1));
}

// ---------------- bf16x3 plane GEMM, cp.async double buffer, opt. split-K ----------------
// C[m][n] = sum_k A[m][k]*W[n][k]; A,W given as bf16 hi/lo planes, lda = ldb = K.
// SK > 1: blockIdx.z = k-split index; plain partial store to C + z*M*N (EPI ignored).
// EPI: 0 plain, 1 softplus(acc+bias[n]), 2 transpose+residual to d_out.
template<int BM, int BN, int WM, int WN, int EPI, int SK>
__global__ void __launch_bounds__(256, 2)
pgemm_k(const __nv_bfloat16* __restrict__ Ah, const __nv_bfloat16* __restrict__ Al,
        const __nv_bfloat16* __restrict__ Bh, const __nv_bfloat16* __restrict__ Bl,
        float* __restrict__ C, int M, int N, int K,
        const float* __restrict__ ep_bias, const float* __restrict__ ep_res)
{
    constexpr int BK  = 32;
    constexpr int RB  = 80;                 // smem row bytes: 64 data + 16 pad
    constexpr int PLA = BM * RB;
    constexpr int PLB = BN * RB;
    constexpr int STG = 2 * PLA + 2 * PLB;  // Ahi|Alo|Bhi|Blo
    constexpr int WTM = BM / WM, WTN = BN / WN;
    constexpr int MF  = WTM / 16, NF = WTN / 8;
    constexpr int ACH = BM * 8;
    constexpr int BCH = BN * 8;

    extern __shared__ char smem[];
    const uint32_t s0 = smem_u32(smem);

    const int tid  = threadIdx.x;
    const int warp = tid >> 5, lane = tid & 31;
    const int grp  = lane >> 2, tid4 = lane & 3;
    const int warpM = warp % WM, warpN = warp / WM;
    const int mBase = warpM * WTM, nBase = warpN * WTN;
    const int m0 = blockIdx.y * BM, n0 = blockIdx.x * BN;
    const int kbase = (SK > 1) ? blockIdx.z * (K / SK) : 0;
    const int Kp = K / SK;

    float acc[MF][NF][4];
    #pragma unroll
    for (int i = 0; i < MF; i++)
        #pragma unroll
        for (int j = 0; j < NF; j++)
            #pragma unroll
            for (int r = 0; r < 4; r++) acc[i][j][r] = 0.f;

    auto load_stage = [&](int st, int k0) {
        const uint32_t dA = s0 + st * STG;
        for (int t = tid; t < ACH; t += 256) {
            const int row = t >> 3, c = t & 7, pl = c >> 2, ch = c & 3;
            const __nv_bfloat16* src = (pl ? Al : Ah)
                + (size_t)(m0 + row) * K + k0 + ch * 8;
            cp16(dA + pl * PLA + row * RB + ch * 16, src);
        }
        const uint32_t dB = s0 + st * STG + 2 * PLA;
        for (int t = tid; t < BCH; t += 256) {
            const int row = t >> 3, c = t & 7, pl = c >> 2, ch = c & 3;
            const __nv_bfloat16* src = (pl ? Bl : Bh)
                + (size_t)(n0 + row) * K + k0 + ch * 8;
            cp16(dB + pl * PLB + row * RB + ch * 16, src);
        }
    };

    const int KT = Kp / BK;
    load_stage(0, kbase);
    CP_COMMIT();

    for (int it = 0; it < KT; it++) {
        CP_WAIT0();
        __syncthreads();
        if (it + 1 < KT) { load_stage((it + 1) & 1, kbase + (it + 1) * BK); CP_COMMIT(); }

        const uint32_t sA = s0 + (it & 1) * STG;
        const uint32_t sB = sA + 2 * PLA;

        #pragma unroll
        for (int ks = 0; ks < 2; ks++) {
            const int kw = (ks * 8 + tid4) * 4;
            uint32_t ah[MF][4], al_[MF][4];
            #pragma unroll
            for (int mt = 0; mt < MF; mt++) {
                const uint32_t a0 = sA + (mBase + mt * 16 + grp) * RB + kw;
                ah[mt][0]  = lds32(a0);
                ah[mt][1]  = lds32(a0 + 8 * RB);
                ah[mt][2]  = lds32(a0 + 16);
                ah[mt][3]  = lds32(a0 + 8 * RB + 16);
                const uint32_t a1 = a0 + PLA;
                al_[mt][0] = lds32(a1);
                al_[mt][1] = lds32(a1 + 8 * RB);
                al_[mt][2] = lds32(a1 + 16);
                al_[mt][3] = lds32(a1 + 8 * RB + 16);
            }
            uint32_t bh[NF][2], bl_[NF][2];
            #pragma unroll
            for (int nt = 0; nt < NF; nt++) {
                const uint32_t b0 = sB + (nBase + nt * 8 + grp) * RB + kw;
                bh[nt][0]  = lds32(b0);
                bh[nt][1]  = lds32(b0 + 16);
                const uint32_t b1 = b0 + PLB;
                bl_[nt][0] = lds32(b1);
                bl_[nt][1] = lds32(b1 + 16);
            }
            #pragma unroll
            for (int mt = 0; mt < MF; mt++)
                #pragma unroll
                for (int nt = 0; nt < NF; nt++) {
                    mma_bf16(acc[mt][nt], ah[mt][0], ah[mt][1], ah[mt][2], ah[mt][3],
                             bl_[nt][0], bl_[nt][1]);
                    mma_bf16(acc[mt][nt], al_[mt][0], al_[mt][1], al_[mt][2], al_[mt][3],
                             bh[nt][0], bh[nt][1]);
                    mma_bf16(acc[mt][nt], ah[mt][0], ah[mt][1], ah[mt][2], ah[mt][3],
                             bh[nt][0], bh[nt][1]);
                }
        }
        __syncthreads();
    }

    // epilogue
    float* Cw = (SK > 1) ? C + (size_t)blockIdx.z * (size_t)M * N : C;
    #pragma unroll
    for (int mt = 0; mt < MF; mt++) {
        #pragma unroll
        for (int nt = 0; nt < NF; nt++) {
            #pragma unroll
            for (int r = 0; r < 4; r++) {
                const int m = m0 + mBase + mt * 16 + grp + ((r >= 2) ? 8 : 0);
                const int n = n0 + nBase + nt * 8 + tid4 * 2 + (r & 1);
                if (n < N) {
                    float v = acc[mt][nt][r];
                    if (SK > 1) {
                        Cw[(size_t)m * N + n] = v;
                    } else if (EPI == 1) {
                        v += ep_bias[n];
                        v = fmaxf(v, 0.f) + log1pf(expf(-fabsf(v)));   // stable softplus
                        Cw[(size_t)m * N + n] = v;
                    } else if (EPI == 2) {
                        const int b = m >> 10, l = m & 1023;
                        const size_t o = (size_t)b * (size_t)N * LSEQ + (size_t)n * LSEQ + l;
                        Cw[o] = v + ep_res[o];
                    } else {
                        Cw[(size_t)m * N + n] = v;
                    }
                }
            }
        }
    }
}

// ---------------- split-K reduce for x_proj (+ dt_raw bf16 planes) ----------------
__global__ void redx_k(const float* __restrict__ part, float* __restrict__ xdbl,
                       __nv_bfloat16* __restrict__ dtH, __nv_bfloat16* __restrict__ dtL)
{
    const int idx = blockIdx.x * 256 + threadIdx.x;   // < MROWS*NDBL
    if (idx >= MROWS * NDBL) return;
    float s = 0.f;
    #pragma unroll
    for (int p = 0; p < XPSK; p++)
        s += part[(size_t)p * MROWS * NDBL + idx];
    xdbl[idx] = s;
    const int n = idx % NDBL;
    if (n < DTRANK) {
        const int m = idx / NDBL;
        const __nv_bfloat16 h = __float2bfloat16(s);
        dtH[(size_t)m * DTRANK + n] = h;
        dtL[(size_t)m * DTRANK + n] = __float2bfloat16(s - __bfloat162float(h));
    }
}

// ---------------- depthwise causal conv (k=4) + bias + SiLU (+ planes) ----------------
__global__ void conv_silu_k(const float* __restrict__ xz, const float* __restrict__ cw,
                            const float* __restrict__ cb, float* __restrict__ xc,
                            __nv_bfloat16* __restrict__ xcH, __nv_bfloat16* __restrict__ xcL)
{
    const int idx = blockIdx.x * blockDim.x + threadIdx.x;
    const int d = idx & (DINNER - 1);
    const int m = idx >> 11;
    const int l = m & (LSEQ - 1);

    float acc = cb[d];
    #pragma unroll
    for (int j = 0; j < 4; j++) {
        const int ll = l - 3 + j;
        if (ll >= 0)
            acc = fmaf(cw[d * 4 + j], xz[(size_t)(m - 3 + j) * NXZ + d], acc);
    }
    acc = acc / (1.f + __expf(-acc));
    xc[idx] = acc;
    const __nv_bfloat16 h = __float2bfloat16(acc);
    xcH[idx] = h;
    xcL[idx] = __float2bfloat16(acc - __bfloat162float(h));
}

// ================= parallel chunked selective scan =================
__global__ void scan_part_k(const float* __restrict__ dt, const float* __restrict__ xc,
                            const float* __restrict__ xdbl, const float* __restrict__ A_log,
                            float* __restrict__ Ap_out, float* __restrict__ Hp_out)
{
    const int d = blockIdx.x * 128 + threadIdx.x;
    const int c = blockIdx.y;
    const int b = blockIdx.z;

    __shared__ float Bsh[CLEN][DSTATE];
    #pragma unroll
    for (int t = threadIdx.x; t < CLEN * DSTATE; t += 128) {
        const int l = t >> 4, i = t & 15;
        Bsh[l][i] = xdbl[(size_t)(b * LSEQ + c * CLEN + l) * NDBL + DTRANK + i];
    }
    __syncthreads();

    float a[DSTATE], Ap[DSTATE], h[DSTATE];
    #pragma unroll
    for (int s = 0; s < DSTATE; s++) {
        a[s]  = -expf(A_log[(size_t)d * DSTATE + s]);
        Ap[s] = 1.f;
        h[s]  = 0.f;
    }

    for (int l = 0; l < CLEN; l++) {
        const int m = b * LSEQ + c * CLEN + l;
        const float dtv = dt[(size_t)m * DINNER + d];
        const float xv  = xc[(size_t)m * DINNER + d];
        const float dtx = dtv * xv;
        #pragma unroll
        for (int s = 0; s < DSTATE; s++) {
            const float da = __expf(dtv * a[s]);
            Ap[s] *= da;
            h[s]   = fmaf(da, h[s], dtx * Bsh[l][s]);
        }
    }
    #pragma unroll
    for (int s = 0; s < DSTATE; s++) {
        const size_t o = ((size_t)((b * NCHUNK + c) * DSTATE + s) << 11) + d;
        Ap_out[o] = Ap[s];
        Hp_out[o] = h[s];
    }
}

__global__ void scan_mid_k(const float* __restrict__ Ap, const float* __restrict__ Hp,
                           float* __restrict__ hin)
{
    const int idx = blockIdx.x * 256 + threadIdx.x;
    const int d = idx & (DINNER - 1);
    const int s = (idx >> 11) & (DSTATE - 1);
    const int b = idx >> 15;

    float h = 0.f;
    #pragma unroll
    for (int c = 0; c < NCHUNK; c++) {
        const size_t o = ((size_t)((b * NCHUNK + c) * DSTATE + s) << 11) + d;
        hin[o] = h;
        h = fmaf(Ap[o], h, Hp[o]);
    }
}

__global__ void scan_out_k(const float* __restrict__ dt, const float* __restrict__ xc,
                           const float* __restrict__ xdbl, const float* __restrict__ xz,
                           const float* __restrict__ A_log, const float* __restrict__ Dp,
                           const float* __restrict__ hin,
                           __nv_bfloat16* __restrict__ yH, __nv_bfloat16* __restrict__ yL)
{
    const int d = blockIdx.x * 128 + threadIdx.x;
    const int c = blockIdx.y;
    const int b = blockIdx.z;

    __shared__ float Bsh[CLEN][DSTATE];
    __shared__ float Csh[CLEN][DSTATE];
    #pragma unroll
    for (int t = threadIdx.x; t < CLEN * 2 * DSTATE; t += 128) {
        const int l = t >> 5, i = t & 31;
        const float v = xdbl[(size_t)(b * LSEQ + c * CLEN + l) * NDBL + DTRANK + i];
        if (i < DSTATE) Bsh[l][i] = v;
        else            Csh[l][i - DSTATE] = v;
    }
    __syncthreads();

    float a[DSTATE], h[DSTATE];
    #pragma unroll
    for (int s = 0; s < DSTATE; s++) {
        a[s] = -expf(A_log[(size_t)d * DSTATE + s]);
        const size_t o = ((size_t)((b * NCHUNK + c) * DSTATE + s) << 11) + d;
        h[s] = hin[o];
    }
    const float Dd = Dp[d];

    for (int l = 0; l < CLEN; l++) {
        const int m = b * LSEQ + c * CLEN + l;
        const float dtv = dt[(size_t)m * DINNER + d];
        const float xv  = xc[(size_t)m * DINNER + d];
        const float dtx = dtv * xv;
        float y = 0.f;
        #pragma unroll
        for (int s = 0; s < DSTATE; s++) {
            const float da = __expf(dtv * a[s]);
            h[s] = fmaf(da, h[s], dtx * Bsh[l][s]);
            y    = fmaf(h[s], Csh[l][s], y);
        }
        const float zv = xz[(size_t)m * NXZ + DINNER + d];
        const float sz = zv / (1.f + __expf(-zv));
        const float yo = (y + xv * Dd) * sz;
        const __nv_bfloat16 hh = __float2bfloat16(yo);
        yH[(size_t)m * DINNER + d] = hh;
        yL[(size_t)m * DINNER + d] = __float2bfloat16(yo - __bfloat162float(hh));
    }
}

// ---------------- driver ----------------
extern "C" void kernel_launch(void* const* d_in, const int* in_sizes, int n_in,
                              void* d_out, int out_size)
{
    const float* x    = (const float*)d_in[0];
    const float* lnw  = (const float*)d_in[1];
    const float* lnb  = (const float*)d_in[2];
    const float* win  = (const float*)d_in[3];
    const float* cw   = (const float*)d_in[4];
    const float* cb   = (const float*)d_in[5];
    const float* wx   = (const float*)d_in[6];
    const float* wdt  = (const float*)d_in[7];
    const float* bdt  = (const float*)d_in[8];
    const float* alog = (const float*)d_in[9];
    const float* Dp   = (const float*)d_in[10];
    const float* wout = (const float*)d_in[11];
    float* out = (float*)d_out;

    float *xn, *xz, *xc, *xdbl, *dtb, *ap, *hp, *hin, *part;
    cudaGetSymbolAddress((void**)&xn,   g_xn);
    cudaGetSymbolAddress((void**)&xz,   g_xz);
    cudaGetSymbolAddress((void**)&xc,   g_xc);
    cudaGetSymbolAddress((void**)&xdbl, g_xdbl);
    cudaGetSymbolAddress((void**)&dtb,  g_dt);
    cudaGetSymbolAddress((void**)&ap,   g_Ap);
    cudaGetSymbolAddress((void**)&hp,   g_Hp);
    cudaGetSymbolAddress((void**)&hin,  g_hin);
    cudaGetSymbolAddress((void**)&part, g_part);

    __nv_bfloat16 *winH,*winL,*wxH,*wxL,*wdtH,*wdtL,*woutH,*woutL;
    __nv_bfloat16 *xnH,*xnL,*xcH,*xcL,*dtAH,*dtAL,*yH,*yL;
    cudaGetSymbolAddress((void**)&winH, g_winH);  cudaGetSymbolAddress((void**)&winL, g_winL);
    cudaGetSymbolAddress((void**)&wxH,  g_wxH);   cudaGetSymbolAddress((void**)&wxL,  g_wxL);
    cudaGetSymbolAddress((void**)&wdtH, g_wdtH);  cudaGetSymbolAddress((void**)&wdtL, g_wdtL);
    cudaGetSymbolAddress((void**)&woutH,g_woutH); cudaGetSymbolAddress((void**)&woutL,g_woutL);
    cudaGetSymbolAddress((void**)&xnH,  g_xnH);   cudaGetSymbolAddress((void**)&xnL,  g_xnL);
    cudaGetSymbolAddress((void**)&xcH,  g_xcH);   cudaGetSymbolAddress((void**)&xcL,  g_xcL);
    cudaGetSymbolAddress((void**)&dtAH, g_dtAH);  cudaGetSymbolAddress((void**)&dtAL, g_dtAL);
    cudaGetSymbolAddress((void**)&yH,   g_yH);    cudaGetSymbolAddress((void**)&yL,   g_yL);

    // dynamic SMEM (2 stages x (2*BM + 2*BN) rows x 80B)
    const int SM_128_128 = 2 * 2 * (128 + 128) * 80;  // 81920
    const int SM_128_64  = 2 * 2 * (128 + 64)  * 80;  // 61440
    const int SM_64_96   = 2 * 2 * (64 + 96)   * 80;  // 51200
    cudaFuncSetAttribute(pgemm_k<128,128,2,4,0,1>, cudaFuncAttributeMaxDynamicSharedMemorySize, SM_128_128);
    cudaFuncSetAttribute(pgemm_k<128,128,2,4,1,1>, cudaFuncAttributeMaxDynamicSharedMemorySize, SM_128_128);
    cudaFuncSetAttribute(pgemm_k<128,64,2,4,2,1>,  cudaFuncAttributeMaxDynamicSharedMemorySize, SM_128_64);
    cudaFuncSetAttribute(pgemm_k<64,96,2,4,0,XPSK>,cudaFuncAttributeMaxDynamicSharedMemorySize, SM_64_96);

    // 0. weight planes (per call; deterministic)
    cvt_k<<<(NXZ*DMODEL/4 + 255)/256, 256>>>((const float4*)win,  (__nv_bfloat162*)winH,  (__nv_bfloat162*)winL,  NXZ*DMODEL/4);
    cvt_k<<<(NDBL*DINNER/4 + 255)/256, 256>>>((const float4*)wx,  (__nv_bfloat162*)wxH,   (__nv_bfloat162*)wxL,   NDBL*DINNER/4);
    cvt_k<<<(DINNER*DTRANK/4 + 255)/256, 256>>>((const float4*)wdt,(__nv_bfloat162*)wdtH, (__nv_bfloat162*)wdtL,  DINNER*DTRANK/4);
    cvt_k<<<(DMODEL*DINNER/4 + 255)/256, 256>>>((const float4*)wout,(__nv_bfloat162*)woutH,(__nv_bfloat162*)woutL, DMODEL*DINNER/4);

    // 1. transpose (B,C,L) -> (B,L,C)
    transpose_k<<<dim3(LSEQ/32, DMODEL/32, BATCH), dim3(32, 8)>>>(x, xn);
    // 2. layernorm -> xn planes
    ln_k<<<MROWS, 256>>>(xn, lnw, lnb, xnH, xnL);
    // 3. in_proj: (2048x1024) x (4096x1024)^T -> xz
    pgemm_k<128,128,2,4,0,1><<<dim3(NXZ/128, MROWS/128), 256, SM_128_128>>>(
        xnH, xnL, winH, winL, xz, MROWS, NXZ, DMODEL, nullptr, nullptr);
    // 4. depthwise conv + silu -> xc fp32 + planes
    conv_silu_k<<<(MROWS*DINNER)/256, 256>>>(xz, cw, cb, xc, xcH, xcL);
    // 5. x_proj split-K x8 -> partials, then reduce (+ dt_raw planes)
    pgemm_k<64,96,2,4,0,XPSK><<<dim3(1, MROWS/64, XPSK), 256, SM_64_96>>>(
        xcH, xcL, wxH, wxL, part, MROWS, NDBL, DINNER, nullptr, nullptr);
    redx_k<<<(MROWS*NDBL + 255)/256, 256>>>(part, xdbl, dtAH, dtAL);
    // 6. dt_proj + softplus -> dt fp32
    pgemm_k<128,128,2,4,1,1><<<dim3(DINNER/128, MROWS/128), 256, SM_128_128>>>(
        dtAH, dtAL, wdtH, wdtL, dtb, MROWS, DINNER, DTRANK, bdt, nullptr);
    // 7-9. parallel chunked selective scan -> yout planes
    scan_part_k<<<dim3(DINNER/128, NCHUNK, BATCH), 128>>>(dtb, xc, xdbl, alog, ap, hp);
    scan_mid_k<<<(BATCH*DSTATE*DINNER)/256, 256>>>(ap, hp, hin);
    scan_out_k<<<dim3(DINNER/128, NCHUNK, BATCH), 128>>>(dtb, xc, xdbl, xz, alog, Dp, hin, yH, yL);
    // 10. out_proj (BN=64, full wave) + transpose-store + residual
    pgemm_k<128,64,2,4,2,1><<<dim3(DMODEL/64, MROWS/128), 256, SM_128_64>>>(
        yH, yL, woutH, woutL, out, MROWS, DMODEL, DINNER, nullptr, x);
}